// round 10
// baseline (speedup 1.0000x reference)
#include <cuda_runtime.h>
#include <cstdint>

#define D_DIM   2048
#define NROWS   16
#define TOKENS  32768
#define T_TOK   6                    // tokens per warp-pair tile
#define NTILES  ((TOKENS + T_TOK - 1) / T_TOK)   // 5462 (last tile clamped/overlapping)
#define BLOCK   384
#define GRID    152
#define NPAIRS_CTA (BLOCK / 64)      // 6 warp-pairs per CTA
#define SMEM_W   (NROWS * D_DIM * 4) // 131072 bytes for weights
#define XCH_FLOATS (NPAIRS_CTA * 2 * T_TOK * 4)  // pair x parity x tok x 4
#define SMEM_BYTES (SMEM_W + XCH_FLOATS * 4)

__device__ __forceinline__ void ffma2(unsigned long long &acc,
                                      unsigned long long a,
                                      unsigned long long b) {
    asm("fma.rn.f32x2 %0, %1, %2, %0;" : "+l"(acc) : "l"(a), "l"(b));
}

// Load one 128-float block (T_TOK tokens, this lane's 4 floats each) into regs.
#define LOADX(buf, xq, blk)                                                    \
    {                                                                          \
        _Pragma("unroll")                                                      \
        for (int t = 0; t < T_TOK; t++)                                        \
            buf[t] = *reinterpret_cast<const ulonglong2*>(                     \
                (xq) + (size_t)t * D_DIM + (blk) * 128);                       \
    }

// FMA one block: this warp's 8 rows x T_TOK tokens.
#define COMPUTE8(buf, wq, blkoff)                                              \
    {                                                                          \
        _Pragma("unroll")                                                      \
        for (int r = 0; r < 8; r++) {                                          \
            ulonglong2 wv = *reinterpret_cast<const ulonglong2*>(              \
                (wq) + r * D_DIM + (blkoff));                                  \
            _Pragma("unroll")                                                  \
            for (int t = 0; t < T_TOK; t++) {                                  \
                ffma2(acc[r][t], buf[t].x, wv.x);                              \
                ffma2(acc[r][t], buf[t].y, wv.y);                              \
            }                                                                  \
        }                                                                      \
    }

extern "C" __global__ void __launch_bounds__(BLOCK, 1)
router_kernel(const float* __restrict__ x,
              const float* __restrict__ W1,
              const float* __restrict__ W2,
              float* __restrict__ out)
{
    extern __shared__ float Wsh[];           // rows 0..7 = W1, 8..15 = W2
    float* xch = Wsh + NROWS * D_DIM;        // pair exchange slots

    {
        int tid = threadIdx.x;
        for (int idx = tid * 4; idx < 8 * D_DIM; idx += BLOCK * 4) {
            *reinterpret_cast<float4*>(Wsh + idx) =
                *reinterpret_cast<const float4*>(W1 + idx);
            *reinterpret_cast<float4*>(Wsh + 8 * D_DIM + idx) =
                *reinterpret_cast<const float4*>(W2 + idx);
        }
        __syncthreads();
    }

    const int lane        = threadIdx.x & 31;
    const int wid         = threadIdx.x >> 5;
    const int pair_in_cta = wid >> 1;
    const int role        = wid & 1;          // 0 = group rows (W1), 1 = expert rows (W2)
    const int gpair       = blockIdx.x * NPAIRS_CTA + pair_in_cta;
    const int npairs      = GRID * NPAIRS_CTA;
    const int bar_id      = 8 + pair_in_cta;

    const float* wp = Wsh + role * 8 * D_DIM + lane * 4;

    int iterpar = 0;
    for (int tile = gpair; tile < NTILES; tile += npairs, iterpar ^= 1) {
        // Clamp the last tile so it fully fits: overlapping tokens are
        // recomputed identically by two pairs -> byte-identical stores, safe.
        const int tok0 = min(tile * T_TOK, TOKENS - T_TOK);
        const float* xp = x + (size_t)tok0 * D_DIM + lane * 4;

        unsigned long long acc[8][T_TOK];
        #pragma unroll
        for (int r = 0; r < 8; r++)
            #pragma unroll
            for (int t = 0; t < T_TOK; t++)
                acc[r][t] = 0ull;

        // depth-2 x prefetch pipeline over 16 blocks of 128 floats
        ulonglong2 b0[T_TOK], b1[T_TOK];
        LOADX(b0, xp, 0);
        LOADX(b1, xp, 1);

        const float* wq = wp;
        const float* xq = xp;
        #pragma unroll 1
        for (int i = 0; i < 16; i += 2) {
            COMPUTE8(b0, wq, 0);
            if (i < 14) LOADX(b0, xq, 2);
            COMPUTE8(b1, wq, 128);
            if (i < 14) LOADX(b1, xq, 3);
            wq += 256;
            xq += 256;
        }

        // Split-lane reduction: row pairs (rp, rp+4). Lanes 0-15 finish row rp,
        // lanes 16-31 finish row rp+4. 6 shfl per (pair, token).
        float lo[4] = {0.f, 0.f, 0.f, 0.f};
        float hi[4] = {0.f, 0.f, 0.f, 0.f};
        #pragma unroll
        for (int rp = 0; rp < 4; rp++) {
            #pragma unroll
            for (int t = 0; t < T_TOK; t++) {
                float2 fa = *reinterpret_cast<float2*>(&acc[rp][t]);
                float2 fb = *reinterpret_cast<float2*>(&acc[rp + 4][t]);
                float a = fa.x + fa.y;
                float b = fb.x + fb.y;
                float ta = __shfl_xor_sync(0xffffffffu, a, 16);
                float tb = __shfl_xor_sync(0xffffffffu, b, 16);
                float v = (lane & 16) ? (b + tb) : (a + ta);
                v += __shfl_xor_sync(0xffffffffu, v, 8);
                v += __shfl_xor_sync(0xffffffffu, v, 4);
                v += __shfl_xor_sync(0xffffffffu, v, 2);
                v += __shfl_xor_sync(0xffffffffu, v, 1);
                if (lane == t)      lo[rp] = v;
                if (lane == 16 + t) hi[rp] = v;
            }
        }
        // Lane t gathers rows 4-7 from lane 16+t.
        float s[8];
        #pragma unroll
        for (int rp = 0; rp < 4; rp++) {
            s[rp]     = lo[rp];
            s[rp + 4] = __shfl_xor_sync(0xffffffffu, hi[rp], 16);
        }

        // top-2 of 8 (lax.top_k tie rule: lowest index wins). Valid on lanes 0..T_TOK-1.
        float v1 = s[0]; int i1 = 0;
        #pragma unroll
        for (int k = 1; k < 8; k++) if (s[k] > v1) { v1 = s[k]; i1 = k; }
        float v2 = -3.402823466e+38f; int i2 = 0;
        #pragma unroll
        for (int k = 0; k < 8; k++) if (k != i1 && s[k] > v2) { v2 = s[k]; i2 = k; }

        float* slot = xch + (((pair_in_cta << 1) | iterpar) * T_TOK + lane) * 4;

        if (role == 1 && lane < T_TOK) {      // expert warp publishes its top-2
            slot[0] = v1;
            slot[1] = v2;
            reinterpret_cast<int*>(slot)[2] = i1 * 8 + i2;
        }

        asm volatile("bar.sync %0, %1;" :: "r"(bar_id), "r"(64) : "memory");

        if (role == 0 && lane < T_TOK) {      // group warp finishes the token
            const int tok = tok0 + lane;
            const float g1v = v1, g2v = v2;
            const int   g1 = i1, g2 = i2;
            const float e1v = slot[0];
            const float e2v = slot[1];
            const int   eid = reinterpret_cast<int*>(slot)[2];
            const int   e1 = eid >> 3, e2 = eid & 7;

            const float c0 = g1v + e1v;
            const float c1 = g1v + e2v;
            const float c2 = g2v + e1v;
            const float c3 = g2v + e2v;
            const float m  = fmaxf(fmaxf(c0, c1), fmaxf(c2, c3));
            float w0 = __expf(c0 - m);
            float w1 = __expf(c1 - m);
            float w2 = __expf(c2 - m);
            float w3 = __expf(c3 - m);
            const float inv = 1.0f / (w0 + w1 + w2 + w3);
            w0 *= inv; w1 *= inv; w2 *= inv; w3 *= inv;

            float4 idxv = make_float4((float)(g1 * 8 + e1), (float)(g1 * 8 + e2),
                                      (float)(g2 * 8 + e1), (float)(g2 * 8 + e2));
            float4 wv4  = make_float4(w0, w1, w2, w3);

            *reinterpret_cast<float4*>(out + (size_t)tok * 4) = idxv;
            *reinterpret_cast<float4*>(out + (size_t)TOKENS * 4 + (size_t)tok * 4) = wv4;
        }
    }
}

extern "C" void kernel_launch(void* const* d_in, const int* in_sizes, int n_in,
                              void* d_out, int out_size) {
    const float* x  = (const float*)d_in[0];
    const float* W1 = (const float*)d_in[1];
    const float* W2 = (const float*)d_in[2];
    float* out = (float*)d_out;

    cudaFuncSetAttribute(router_kernel,
                         cudaFuncAttributeMaxDynamicSharedMemorySize, SMEM_BYTES);
    router_kernel<<<GRID, BLOCK, SMEM_BYTES>>>(x, W1, W2, out);
}